// round 6
// baseline (speedup 1.0000x reference)
#include <cuda_runtime.h>
#include <cstdint>
#include <cstddef>

#define T_STEPS 512
#define B_SZ    128
#define EMB_D   256
#define HID     512
#define VOCAB   50257
#define GM      16    // batch groups
#define GS      8     // column slices
#define MB      8     // batches per group
#define NJ      64    // columns per slice
// scan smem strides
#define WS      1024  // UwT slice stride (floats): [32][16kk x 64j]
#define HS      132   // hsm slice stride (floats): 528 B == 16 mod 128
#define PS      520   // P row stride (ull): == 8 mod 16

typedef unsigned long long ull;

// ---------------------------------------------------------------------------
// Static device scratch
// ---------------------------------------------------------------------------
__device__ __align__(16) float g_wx[(size_t)T_STEPS * B_SZ * HID];   // 128 MB
__device__ __align__(16) float g_h[2][GM][HID][MB];                  // [slot][g][j][b]
__device__ int g_flags[GM * GS][32];                                 // 128 B per flag

// ---------------------------------------------------------------------------
// f32x2 helpers
// ---------------------------------------------------------------------------
__device__ __forceinline__ ull pack2(float x) {
    ull r;
    asm("mov.b64 %0, {%1, %1};" : "=l"(r) : "f"(x));
    return r;
}
__device__ __forceinline__ void ffma2(ull& d, ull a, ull b) {
    asm("fma.rn.f32x2 %0, %1, %2, %0;" : "+l"(d) : "l"(a), "l"(b));
}
__device__ __forceinline__ void add2(ull& d, ull a) {
    asm("add.rn.f32x2 %0, %0, %1;" : "+l"(d) : "l"(a));
}
__device__ __forceinline__ float2 unpack2(ull v) {
    float2 f;
    asm("mov.b64 {%0, %1}, %2;" : "=f"(f.x), "=f"(f.y) : "l"(v));
    return f;
}
__device__ __forceinline__ float fast_tanh(float x) {
    float e = __expf(2.0f * x);
    return 1.0f - __fdividef(2.0f, e + 1.0f);
}

// ---------------------------------------------------------------------------
// Kernel A: wx[t,b,j] = Wb[j] + sum_e emb[x[b,t],e] * Ww[j,e]  (unchanged)
// ---------------------------------------------------------------------------
__global__ void __launch_bounds__(256) wx_kernel(const int* __restrict__ x32,
                                                 const float* __restrict__ emb,
                                                 const float* __restrict__ Ww,
                                                 const float* __restrict__ Wb) {
    extern __shared__ float sm[];
    float* A_s = sm;                         // [128][256]
    float* W_s = sm + 128 * EMB_D;           // [256][68]
    __shared__ int tok_s[128];

    const int t   = blockIdx.x >> 3;
    const int n0  = (blockIdx.x & 7) * NJ;
    const int tid = threadIdx.x;

    if (blockIdx.x == 0 && tid < GM * GS) g_flags[tid][0] = 0;

    int lo = 0, hi = 0;
    if (tid < 128) {
        size_t idx = (size_t)tid * T_STEPS + t;
        lo = x32[2 * idx];
        hi = x32[2 * idx + 1];
    }
    int ok = (tid < 128) ? (hi == 0 && (unsigned)lo < VOCAB) : 1;
    int is64 = __syncthreads_and(ok);
    if (tid < 128) tok_s[tid] = is64 ? lo : x32[(size_t)tid * T_STEPS + t];

    for (int i = tid; i < NJ * EMB_D; i += 256) {
        int jl = i >> 8, e = i & 255;
        W_s[e * 68 + jl] = Ww[(size_t)(n0 + jl) * EMB_D + e];
    }
    __syncthreads();
    for (int i4 = tid; i4 < 128 * (EMB_D / 4); i4 += 256) {
        int b = i4 >> 6, e4 = i4 & 63;
        ((float4*)A_s)[i4] = *(const float4*)&emb[(size_t)tok_s[b] * EMB_D + e4 * 4];
    }
    __syncthreads();

    const int mg = tid >> 4, jg = tid & 15;
    const int j0 = 4 * jg;

    ull acc[8][2];
#pragma unroll
    for (int i = 0; i < 8; i++) { acc[i][0] = 0ULL; acc[i][1] = 0ULL; }

    for (int e0 = 0; e0 < EMB_D; e0 += 4) {
        float4 av[8];
#pragma unroll
        for (int i = 0; i < 8; i++)
            av[i] = *(const float4*)&A_s[(mg * 8 + i) * EMB_D + e0];
#pragma unroll
        for (int q = 0; q < 4; q++) {
            ulonglong2 w = *(const ulonglong2*)&W_s[(e0 + q) * 68 + j0];
#pragma unroll
            for (int i = 0; i < 8; i++) {
                ull ad = pack2(((const float*)&av[i])[q]);
                ffma2(acc[i][0], ad, w.x);
                ffma2(acc[i][1], ad, w.y);
            }
        }
    }

    const float4 wb = *(const float4*)&Wb[n0 + j0];
    const size_t base = (size_t)t * B_SZ * HID;
#pragma unroll
    for (int i = 0; i < 8; i++) {
        int b = mg * 8 + i;
        float2 p0 = unpack2(acc[i][0]);
        float2 p1 = unpack2(acc[i][1]);
        float4 o = make_float4(p0.x + wb.x, p0.y + wb.y, p1.x + wb.z, p1.y + wb.w);
        *(float4*)&g_wx[base + (size_t)b * HID + n0 + j0] = o;
    }
}

// ---------------------------------------------------------------------------
// Kernel B: persistent recurrence, 512 threads, warp-specialized exchange.
// CTA (g,s): 8 batches x 64 cols. k-loop thread (jg=tid&15, ks=tid>>4):
// 4 cols x 8 batches over 16 k. Reducers = tid<256 (1 output pair each).
// Warps 8-15: per-slice flag poll + slab copy (pipelined across peers).
// ---------------------------------------------------------------------------
__global__ void __launch_bounds__(512, 1) scan_kernel(const float* __restrict__ Uw,
                                                      const float* __restrict__ Ub,
                                                      const float* __restrict__ Vw,
                                                      const float* __restrict__ Vb,
                                                      float* __restrict__ out) {
    extern __shared__ float sm[];
    float* UwT = sm;                                   // [32][WS]   131072 B
    float* hsm = sm + 32 * WS;                         // [32][HS]    16896 B
    ull*   P   = (ull*)(sm + 32 * WS + 32 * HS);       // [16][PS]    66560 B

    const int tid = threadIdx.x;
    const int g = blockIdx.x >> 3, s_ = blockIdx.x & 7;
    const int jg = tid & 15, ks = tid >> 4;

    // UwT[kslice][kk][j] = Uw[64s+j][16*kslice+kk]
    for (int i = tid; i < NJ * HID; i += 512) {
        int jl = i >> 9, k = i & 511;
        UwT[(k >> 4) * WS + (k & 15) * 64 + jl] = Uw[(size_t)(s_ * NJ + jl) * HID + k];
    }
    for (int i = tid; i < 32 * HS; i += 512) hsm[i] = 0.f;   // h_0 = 0

    // Reducer constants (tid < 256): output pair o = (b_r, jp)
    const int b_r = tid >> 5;
    const int jp  = tid & 31;
    const int rbase = (2 * b_r + (jp & 1)) * PS + (jp >> 1);
    const int j0 = s_ * NJ + 2 * jp;
    const int bglob = g * MB + b_r;
    const int myflag = g * GS + s_;
    const float2 ub = (tid < 256) ? *(const float2*)&Ub[j0] : make_float2(0.f, 0.f);
    const int wp = tid >> 5, lane = tid & 31;
    __syncthreads();

    float2 wxv = make_float2(0.f, 0.f);
    if (tid < 256) wxv = *(const float2*)&g_wx[((size_t)0 * B_SZ + bglob) * HID + j0];

    for (int t = 0; t < T_STEPS; t++) {
        // ---- k-loop: 4 cols x 8 batches over 16 k ----
        ull acc[8][2];
#pragma unroll
        for (int b = 0; b < 8; b++) { acc[b][0] = 0ULL; acc[b][1] = 0ULL; }

        const float* hr = &hsm[ks * HS];
        const float* wr = &UwT[ks * WS + 4 * jg];
#pragma unroll
        for (int kk = 0; kk < 16; kk++) {
            float4 ha = *(const float4*)(hr + kk * 8);
            float4 hb = *(const float4*)(hr + kk * 8 + 4);
            ulonglong2 w = *(const ulonglong2*)(wr + kk * 64);
            ull hd;
            hd = pack2(ha.x); ffma2(acc[0][0], hd, w.x); ffma2(acc[0][1], hd, w.y);
            hd = pack2(ha.y); ffma2(acc[1][0], hd, w.x); ffma2(acc[1][1], hd, w.y);
            hd = pack2(ha.z); ffma2(acc[2][0], hd, w.x); ffma2(acc[2][1], hd, w.y);
            hd = pack2(ha.w); ffma2(acc[3][0], hd, w.x); ffma2(acc[3][1], hd, w.y);
            hd = pack2(hb.x); ffma2(acc[4][0], hd, w.x); ffma2(acc[4][1], hd, w.y);
            hd = pack2(hb.y); ffma2(acc[5][0], hd, w.x); ffma2(acc[5][1], hd, w.y);
            hd = pack2(hb.z); ffma2(acc[6][0], hd, w.x); ffma2(acc[6][1], hd, w.y);
            hd = pack2(hb.w); ffma2(acc[7][0], hd, w.x); ffma2(acc[7][1], hd, w.y);
        }

        // ---- partials: P[combo][tid], combo = 2b+u (consecutive-tid: CF) ----
#pragma unroll
        for (int b = 0; b < 8; b++) {
            P[(2 * b + 0) * PS + tid] = acc[b][0];
            P[(2 * b + 1) * PS + tid] = acc[b][1];
        }
        __syncthreads();

        const int slot = (t + 1) & 1;
        if (tid < 256) {
            // ---- reduce 32 k-slices, 4 chains ----
            ull s0 = P[rbase + 16 * 0];
            ull s1 = P[rbase + 16 * 1];
            ull s2 = P[rbase + 16 * 2];
            ull s3 = P[rbase + 16 * 3];
#pragma unroll
            for (int q = 4; q < 32; q += 4) {
                add2(s0, P[rbase + 16 * (q + 0)]);
                add2(s1, P[rbase + 16 * (q + 1)]);
                add2(s2, P[rbase + 16 * (q + 2)]);
                add2(s3, P[rbase + 16 * (q + 3)]);
            }
            add2(s0, s1); add2(s2, s3); add2(s0, s2);
            float2 f = unpack2(s0);
            float o0 = fast_tanh(f.x + wxv.x + ub.x);
            float o1 = fast_tanh(f.y + wxv.y + ub.y);

            // publish to L2 for peers
            float* dst = &g_h[slot][g][0][0];
            dst[(j0 + 0) * MB + b_r] = o0;
            dst[(j0 + 1) * MB + b_r] = o1;
            // own slab straight into hsm (never re-read from L2)
            int haddr = (j0 >> 4) * HS + (j0 & 15) * 8 + b_r;
            hsm[haddr]     = o0;
            hsm[haddr + 8] = o1;
        }
        __syncthreads();

        if (tid == 0) {
            asm volatile("st.release.gpu.global.b32 [%0], %1;"
                         :: "l"(&g_flags[myflag][0]), "r"(t + 1) : "memory");
        }
        if (wp >= 8) {
            // warp (8+sp): wait for peer slice sp, copy its 2 KB slab
            const int sp = wp - 8;
            if (sp != s_) {
                if (lane == 0) {
                    const int* fp = &g_flags[g * GS + sp][0];
                    int v;
                    do {
                        asm volatile("ld.acquire.gpu.global.b32 %0, [%1];"
                                     : "=r"(v) : "l"(fp) : "memory");
                    } while (v < t + 1);
                }
                __syncwarp();
                const float4* src = (const float4*)&g_h[slot][g][0][0];
#pragma unroll
                for (int m = 0; m < 4; m++) {
                    int fidx = lane + 32 * m;
                    float4 v = src[sp * 128 + fidx];
                    int kg = sp * NJ + (fidx >> 1);
                    *(float4*)&hsm[(kg >> 4) * HS + (kg & 15) * 8 + 4 * (fidx & 1)] = v;
                }
            }
        } else if (tid < 256) {
            int tn = (t + 1 < T_STEPS) ? t + 1 : t;
            wxv = *(const float2*)&g_wx[((size_t)tn * B_SZ + bglob) * HID + j0];
        }
        __syncthreads();
    }

    // ---- fused output head: slice-0 CTAs emit logits for their 8 batches ----
    if (s_ == 0 && wp < 8) {
        float a0 = 0.f, a1 = 0.f;
#pragma unroll
        for (int q = 0; q < 16; q++) {
            int k = lane + 32 * q;
            float hv = hsm[(k >> 4) * HS + (k & 15) * 8 + wp];
            a0 += hv * Vw[k];
            a1 += hv * Vw[HID + k];
        }
#pragma unroll
        for (int off = 16; off > 0; off >>= 1) {
            a0 += __shfl_down_sync(0xFFFFFFFFu, a0, off);
            a1 += __shfl_down_sync(0xFFFFFFFFu, a1, off);
        }
        if (lane == 0) {
            out[(g * MB + wp) * 2 + 0] = a0 + Vb[0];
            out[(g * MB + wp) * 2 + 1] = a1 + Vb[1];
        }
    }
}

// ---------------------------------------------------------------------------
// Launch
// ---------------------------------------------------------------------------
extern "C" void kernel_launch(void* const* d_in, const int* in_sizes, int n_in,
                              void* d_out, int out_size) {
    const int*   x32 = (const int*)d_in[0];
    const float* emb = (const float*)d_in[1];
    const float* Ww  = (const float*)d_in[2];
    const float* Wb  = (const float*)d_in[3];
    const float* Uw  = (const float*)d_in[4];
    const float* Ub  = (const float*)d_in[5];
    const float* Vw  = (const float*)d_in[6];
    const float* Vb  = (const float*)d_in[7];
    float* out = (float*)d_out;

    const int smemA = (128 * EMB_D + EMB_D * 68) * (int)sizeof(float);        // 200704
    const int smemB = (32 * WS + 32 * HS) * (int)sizeof(float) + 16 * PS * 8; // 214528
    cudaFuncSetAttribute(wx_kernel,   cudaFuncAttributeMaxDynamicSharedMemorySize, smemA);
    cudaFuncSetAttribute(scan_kernel, cudaFuncAttributeMaxDynamicSharedMemorySize, smemB);

    wx_kernel<<<T_STEPS * 8, 256, smemA>>>(x32, emb, Ww, Wb);
    scan_kernel<<<GM * GS, 512, smemB>>>(Uw, Ub, Vw, Vb, out);
}